// round 17
// baseline (speedup 1.0000x reference)
#include <cuda_runtime.h>
#include <cuda_bf16.h>
#include <cstdint>

// B=8, SEQ=4096, DIM=64.
// out = scale * rope(Q) @ (rope(K)^T @ rope(V))   (associativity; no softmax)
// scale = 1/sqrt(64) = 0.125
// Tensor path: mma.sync.m16n8k16 BF16, 2-way split (3 MMAs) -> ~6e-6 accuracy.
// R17: M split/pack hoisted into the level-2 reduce (done once, not per-CTA).

#define BATCH  8
#define SEQ    4096
#define DIM    64
#define NC     64          // k1 chunks per batch (64 rows each)
#define CH     64
#define NGRP   8

__device__ float    g_partials[NC * BATCH * DIM * DIM];   // 8 MB
__device__ float    g_p2[NGRP * BATCH * DIM * DIM];       // 1 MB
// M pre-split/packed for k3: [b][dim-pair(32)][col4(16)] as uint4 (hi and lo)
__device__ uint4    g_Mh[BATCH * 32 * 16];                // 256 KB
__device__ uint4    g_Ml[BATCH * 32 * 16];

// ---------------------------------------------------------------------------
__device__ __forceinline__ float4 rope4(float4 x, float4 f) {
    float4 o;
    o.x = x.x * f.x - x.y * f.y;  o.y = x.x * f.y + x.y * f.x;
    o.z = x.z * f.z - x.w * f.w;  o.w = x.z * f.w + x.w * f.z;
    return o;
}
// bf16 MMA: D(16x8) += A(16x16) * B(16x8)
__device__ __forceinline__ void mma16(float* c, const uint32_t* a, const uint32_t* b) {
    asm volatile(
        "mma.sync.aligned.m16n8k16.row.col.f32.bf16.bf16.f32 "
        "{%0,%1,%2,%3}, {%4,%5,%6,%7}, {%8,%9}, {%0,%1,%2,%3};\n"
        : "+f"(c[0]), "+f"(c[1]), "+f"(c[2]), "+f"(c[3])
        : "r"(a[0]), "r"(a[1]), "r"(a[2]), "r"(a[3]), "r"(b[0]), "r"(b[1]));
}
// pack (x0 -> lo half, x1 -> hi half) as bf16x2; also emit lo-residual word.
__device__ __forceinline__ void pack2(float x0, float x1, uint32_t& h, uint32_t& l) {
    asm("cvt.rn.bf16x2.f32 %0, %1, %2;" : "=r"(h) : "f"(x1), "f"(x0));
    const float u0 = __uint_as_float(h << 16);
    const float u1 = __uint_as_float(h & 0xFFFF0000u);
    const float l0 = x0 - u0;
    const float l1 = x1 - u1;
    asm("cvt.rn.bf16x2.f32 %0, %1, %2;" : "=r"(l) : "f"(l1), "f"(l0));
}

// ---------------------------------------------------------------------------
// Kernel 1 (R15/R16-verified): partial M = rope(K)^T @ rope(V) over 64 rows.
// 512 CTAs x 128 thr, 4 warps; warp w = M rows 16w..16w+15 x all 64 cols.
// ---------------------------------------------------------------------------
__global__ __launch_bounds__(128) void kv_outer_kernel(
    const float* __restrict__ K, const float* __restrict__ V,
    const float* __restrict__ FK, const float* __restrict__ FV)
{
    const int b = blockIdx.y;
    const int c = blockIdx.x;
    const int t = threadIdx.x;
    const int w = t >> 5;
    const int lane = t & 31;
    const int g = lane >> 2;
    const int tig = lane & 3;

    __shared__ uint32_t skh[32 * 72], skl[32 * 72];   // A hi/lo: 9.2 KB each
    __shared__ uint32_t svh[32 * 72], svl[32 * 72];   // B hi/lo

    const float4* K4  = (const float4*)(K + (size_t)b * SEQ * DIM);
    const float4* V4  = (const float4*)(V + (size_t)b * SEQ * DIM);
    const float4* FK4 = (const float4*)FK;
    const float4* FV4 = (const float4*)FV;

    // staging: 512 items = (32 row-pairs x 16 col4), 4 per thread
#pragma unroll
    for (int u = 0; u < 4; u++) {
        const int f  = t + 128 * u;
        const int rp = f >> 4;          // seq row-pair 0..31
        const int cc = f & 15;          // float4 column
        const int r0 = (c * CH + 2 * rp) * 16 + cc;
        const float4 ka = rope4(K4[r0],      FK4[r0]);
        const float4 kb = rope4(K4[r0 + 16], FK4[r0 + 16]);
        const float4 va = rope4(V4[r0],      FV4[r0]);
        const float4 vb = rope4(V4[r0 + 16], FV4[r0 + 16]);
        uint32_t kh[4], kl[4], vh[4], vl[4];
        pack2(ka.x, kb.x, kh[0], kl[0]); pack2(ka.y, kb.y, kh[1], kl[1]);
        pack2(ka.z, kb.z, kh[2], kl[2]); pack2(ka.w, kb.w, kh[3], kl[3]);
        pack2(va.x, vb.x, vh[0], vl[0]); pack2(va.y, vb.y, vh[1], vl[1]);
        pack2(va.z, vb.z, vh[2], vl[2]); pack2(va.w, vb.w, vh[3], vl[3]);
        const int o = rp * 72 + 4 * cc;
        *(uint4*)&skh[o] = make_uint4(kh[0], kh[1], kh[2], kh[3]);
        *(uint4*)&skl[o] = make_uint4(kl[0], kl[1], kl[2], kl[3]);
        *(uint4*)&svh[o] = make_uint4(vh[0], vh[1], vh[2], vh[3]);
        *(uint4*)&svl[o] = make_uint4(vl[0], vl[1], vl[2], vl[3]);
    }
    __syncthreads();

    const int m0 = 16 * w;

    float acc[8][4];
#pragma unroll
    for (int j = 0; j < 8; j++)
#pragma unroll
        for (int p = 0; p < 4; p++) acc[j][p] = 0.0f;

#pragma unroll
    for (int ks = 0; ks < 4; ks++) {       // 4 x k16 = 64 seq rows
        const int kp0 = ks * 8;
        uint32_t ah[4], al[4];
        ah[0] = skh[(kp0 + tig)     * 72 + m0 + g];
        ah[1] = skh[(kp0 + tig)     * 72 + m0 + g + 8];
        ah[2] = skh[(kp0 + tig + 4) * 72 + m0 + g];
        ah[3] = skh[(kp0 + tig + 4) * 72 + m0 + g + 8];
        al[0] = skl[(kp0 + tig)     * 72 + m0 + g];
        al[1] = skl[(kp0 + tig)     * 72 + m0 + g + 8];
        al[2] = skl[(kp0 + tig + 4) * 72 + m0 + g];
        al[3] = skl[(kp0 + tig + 4) * 72 + m0 + g + 8];
#pragma unroll
        for (int j = 0; j < 8; j++) {
            const int n0 = 8 * j;
            uint32_t bh[2], bl[2];
            bh[0] = svh[(kp0 + tig)     * 72 + n0 + g];
            bh[1] = svh[(kp0 + tig + 4) * 72 + n0 + g];
            bl[0] = svl[(kp0 + tig)     * 72 + n0 + g];
            bl[1] = svl[(kp0 + tig + 4) * 72 + n0 + g];
            mma16(acc[j], ah, bh);
            mma16(acc[j], ah, bl);
            mma16(acc[j], al, bh);
        }
    }

    float* P = g_partials + ((size_t)c * BATCH + b) * (DIM * DIM);
#pragma unroll
    for (int j = 0; j < 8; j++) {
        const int col = 8 * j + 2 * tig;
        *(float2*)&P[(m0 + g)     * DIM + col] = make_float2(acc[j][0], acc[j][1]);
        *(float2*)&P[(m0 + g + 8) * DIM + col] = make_float2(acc[j][2], acc[j][3]);
    }
}

// ---------------------------------------------------------------------------
// Kernel 2a: tree reduce level 1 (64 -> 8 groups). BW-bound.
// ---------------------------------------------------------------------------
__global__ __launch_bounds__(256) void reduce_a_kernel()
{
    const int idx = blockIdx.x * 256 + threadIdx.x;
    const int grp = idx >> 13;
    const int o   = idx & 8191;
    const float4* P = (const float4*)g_partials;
    float4 s0 = make_float4(0.f, 0.f, 0.f, 0.f);
    float4 s1 = make_float4(0.f, 0.f, 0.f, 0.f);
#pragma unroll
    for (int i = 0; i < 8; i += 2) {
        const float4 a = P[(size_t)(grp * 8 + i)     * 8192 + o];
        const float4 e = P[(size_t)(grp * 8 + i + 1) * 8192 + o];
        s0.x += a.x; s0.y += a.y; s0.z += a.z; s0.w += a.w;
        s1.x += e.x; s1.y += e.y; s1.z += e.z; s1.w += e.w;
    }
    ((float4*)g_p2)[(size_t)grp * 8192 + o] =
        make_float4(s0.x + s1.x, s0.y + s1.y, s0.z + s1.z, s0.w + s1.w);
}

// ---------------------------------------------------------------------------
// Kernel 2b: level-2 reduce + SPLIT + PACK (once, L2-hot).
// 4096 threads; thread (b, kp, cc) sums 8 group-partials for M rows 2kp and
// 2kp+1 at col4 cc, then packs bf16 hi/lo row-pair words for k3.
// ---------------------------------------------------------------------------
__global__ __launch_bounds__(256) void reduce_b_kernel()
{
    const int idx = blockIdx.x * 256 + threadIdx.x;   // 0..4095
    const int b  = idx >> 9;          // batch
    const int kp = (idx >> 4) & 31;   // dim pair
    const int cc = idx & 15;          // col4
    const float4* P = (const float4*)g_p2;

    const int oa = b * 1024 + (2 * kp)     * 16 + cc;   // float4 index of row 2kp
    const int ob = b * 1024 + (2 * kp + 1) * 16 + cc;
    float4 ma = make_float4(0.f, 0.f, 0.f, 0.f);
    float4 mb = make_float4(0.f, 0.f, 0.f, 0.f);
#pragma unroll
    for (int i = 0; i < NGRP; i++) {
        const float4 a = P[(size_t)i * 8192 + oa];
        const float4 e = P[(size_t)i * 8192 + ob];
        ma.x += a.x; ma.y += a.y; ma.z += a.z; ma.w += a.w;
        mb.x += e.x; mb.y += e.y; mb.z += e.z; mb.w += e.w;
    }
    uint32_t h[4], l[4];
    pack2(ma.x, mb.x, h[0], l[0]); pack2(ma.y, mb.y, h[1], l[1]);
    pack2(ma.z, mb.z, h[2], l[2]); pack2(ma.w, mb.w, h[3], l[3]);
    g_Mh[idx] = make_uint4(h[0], h[1], h[2], h[3]);
    g_Ml[idx] = make_uint4(l[0], l[1], l[2], l[3]);
}

// ---------------------------------------------------------------------------
// Kernel 3: out = scale * rope(Q) @ M[b].  1024 CTAs x 128 thr; CTA = 32
// q-rows x 64 cols. M staging is a PURE COPY of pre-packed bf16 words
// (L2-hot, zero ALU). q staged coalesced raw (stride 68), A fragments
// packed in-loop from LDS.64 of dim-pairs (R16-verified).
// ---------------------------------------------------------------------------
__global__ __launch_bounds__(128) void qm_kernel(
    const float* __restrict__ Q, const float* __restrict__ FQ,
    float* __restrict__ OUT)
{
    const int b  = blockIdx.y;
    const int rc = blockIdx.x;           // 32-row chunk, 0..127
    const int t  = threadIdx.x;
    const int w  = t >> 5;
    const int lane = t & 31;
    const int g = lane >> 2;
    const int tig = lane & 3;

    __shared__ uint32_t sMh[32 * 72], sMl[32 * 72];   // 9.2 KB each
    __shared__ float sq[32 * 68];                      // 8.7 KB raw rope'd q

    // ---- M staging: pure uint4 copy of pre-packed words ----
    {
        const uint4* MH = g_Mh + b * 512;
        const uint4* ML = g_Ml + b * 512;
#pragma unroll
        for (int u = 0; u < 4; u++) {
            const int f  = t + 128 * u;     // 0..511 = kp*16 + cc
            const int kp = f >> 4;
            const int cc = f & 15;
            const int o = kp * 72 + 4 * cc;
            *(uint4*)&sMh[o] = MH[f];
            *(uint4*)&sMl[o] = ML[f];
        }
    }

    // ---- stage 32 rope'd q rows, coalesced float4 ----
    {
        const float4* Q4  = (const float4*)(Q + ((size_t)b * SEQ + rc * 32) * DIM);
        const float4* F4  = (const float4*)(FQ + (size_t)rc * 32 * DIM);
#pragma unroll
        for (int u = 0; u < 4; u++) {
            const int f  = t + 128 * u;
            const int rr = f >> 4, cc = f & 15;
            *(float4*)&sq[rr * 68 + 4 * cc] = rope4(Q4[f], F4[f]);
        }
    }
    __syncthreads();

    const int m0s = 16 * (w & 1);
    const int nh  = 32 * (w >> 1);

    float cc2[4][4];
#pragma unroll
    for (int j = 0; j < 4; j++)
#pragma unroll
        for (int p = 0; p < 4; p++) cc2[j][p] = 0.0f;

#pragma unroll
    for (int ks = 0; ks < 4; ks++) {     // 4 x k16 = 64 dims
        const int kp0 = ks * 8;
        uint32_t ah[4], al[4];
        {
            const float2 q0 = *(const float2*)&sq[(m0s + g)     * 68 + 2 * (kp0 + tig)];
            const float2 q1 = *(const float2*)&sq[(m0s + g + 8) * 68 + 2 * (kp0 + tig)];
            const float2 q2 = *(const float2*)&sq[(m0s + g)     * 68 + 2 * (kp0 + tig + 4)];
            const float2 q3 = *(const float2*)&sq[(m0s + g + 8) * 68 + 2 * (kp0 + tig + 4)];
            pack2(q0.x, q0.y, ah[0], al[0]);
            pack2(q1.x, q1.y, ah[1], al[1]);
            pack2(q2.x, q2.y, ah[2], al[2]);
            pack2(q3.x, q3.y, ah[3], al[3]);
        }
#pragma unroll
        for (int j = 0; j < 4; j++) {
            const int n0 = nh + 8 * j;
            uint32_t bh[2], bl[2];
            bh[0] = sMh[(kp0 + tig)     * 72 + n0 + g];
            bh[1] = sMh[(kp0 + tig + 4) * 72 + n0 + g];
            bl[0] = sMl[(kp0 + tig)     * 72 + n0 + g];
            bl[1] = sMl[(kp0 + tig + 4) * 72 + n0 + g];
            mma16(cc2[j], ah, bh);
            mma16(cc2[j], ah, bl);
            mma16(cc2[j], al, bh);
        }
    }

    // ---- write 16 rows x 32 cols for this warp ----
    const float scale = 0.125f;   // 1/sqrt(64)
    float* O = OUT + ((size_t)b * SEQ + rc * 32) * DIM;
#pragma unroll
    for (int j = 0; j < 4; j++) {
        const int col = nh + 8 * j + 2 * tig;
        *(float2*)&O[(size_t)(m0s + g)     * DIM + col] =
            make_float2(cc2[j][0] * scale, cc2[j][1] * scale);
        *(float2*)&O[(size_t)(m0s + g + 8) * DIM + col] =
            make_float2(cc2[j][2] * scale, cc2[j][3] * scale);
    }
}

// ---------------------------------------------------------------------------
extern "C" void kernel_launch(void* const* d_in, const int* in_sizes, int n_in,
                              void* d_out, int out_size)
{
    const float* q  = (const float*)d_in[0];
    const float* k  = (const float*)d_in[1];
    const float* v  = (const float*)d_in[2];
    const float* fq = (const float*)d_in[3];
    const float* fk = (const float*)d_in[4];
    const float* fv = (const float*)d_in[5];
    float* out = (float*)d_out;

    kv_outer_kernel<<<dim3(NC, BATCH), 128>>>(k, v, fk, fv);
    reduce_a_kernel<<<256, 256>>>();
    reduce_b_kernel<<<16, 256>>>();
    qm_kernel<<<dim3(SEQ / 32, BATCH), 128>>>(q, fq, out);
}